// round 13
// baseline (speedup 1.0000x reference)
#include <cuda_runtime.h>
#include <math.h>

// ---------------------------------------------------------------------------
// ProposalTarget for GB300.
// Stage 1: per-roi IoU max/argmax vs gt boxes (heavy: 50500 x 500 pairs)
// Stage 2: ordered fg/bg/non-bg index selection (single block, ballot scan)
// Stage 3: materialize rois / one-hot labels / bbox targets (256 slots)
// ---------------------------------------------------------------------------

#define MAXK   1024     // max gt boxes supported
#define MAXTOT 52224    // max total rois (N + K)

__device__ float d_maxov[MAXTOT];
__device__ int   d_assign[MAXTOT];
__device__ int   d_gtcls[MAXK];
__device__ int   d_fg[64];
__device__ int   d_bg[256];
__device__ int   d_nb[256];
__device__ int   d_counts[2];

// ---------------------------------------------------------------------------
// Stage 1: max/argmax IoU per roi + gt class argmax.
// Arithmetic for iw/ih/inter/den follows the reference op order exactly with
// round-to-nearest intrinsics (no FMA contraction) so the threshold-feeding
// quotient bn/bd is bit-identical to the reference's winning IoU.
// Argmax uses cross-multiplied comparison to avoid a divide per pair.
// ---------------------------------------------------------------------------
__global__ __launch_bounds__(256)
void pt_iou_kernel(const float* __restrict__ props,
                   const float* __restrict__ gtb,
                   const float* __restrict__ gtl,
                   int N, int K, int C)
{
    __shared__ float4 sg[MAXK];
    __shared__ float  sarea[MAXK];
    int tid = threadIdx.x;
    for (int k = tid; k < K; k += blockDim.x) {
        float4 b = reinterpret_cast<const float4*>(gtb)[k];
        sg[k] = b;
        float bw = __fadd_rn(__fsub_rn(b.z, b.x), 1.0f);
        float bh = __fadd_rn(__fsub_rn(b.w, b.y), 1.0f);
        sarea[k] = __fmul_rn(bw, bh);
    }
    __syncthreads();

    int idx = blockIdx.x * blockDim.x + tid;
    int n_total = N + K;
    if (idx < n_total) {
        float4 a = (idx < N) ? reinterpret_cast<const float4*>(props)[idx]
                             : reinterpret_cast<const float4*>(gtb)[idx - N];
        float aw = __fadd_rn(__fsub_rn(a.z, a.x), 1.0f);
        float ah = __fadd_rn(__fsub_rn(a.w, a.y), 1.0f);
        float areaA = __fmul_rn(aw, ah);

        float bn = -1.0f;   // best numerator (inter); -1 guarantees k=0 wins first
        float bd = 1.0f;    // best denominator (always > 0 afterwards)
        int   bk = 0;
        #pragma unroll 4
        for (int k = 0; k < K; k++) {
            float4 b = sg[k];
            float iw = fmaxf(__fadd_rn(__fsub_rn(fminf(a.z, b.z), fmaxf(a.x, b.x)), 1.0f), 0.0f);
            float ih = fmaxf(__fadd_rn(__fsub_rn(fminf(a.w, b.w), fmaxf(a.y, b.y)), 1.0f), 0.0f);
            float inter = __fmul_rn(iw, ih);
            float den   = __fsub_rn(__fadd_rn(areaA, sarea[k]), inter);
            // inter/den > bn/bd  <=>  inter*bd > bn*den  (all positive after k=0)
            if (__fmul_rn(inter, bd) > __fmul_rn(bn, den)) {
                bn = inter; bd = den; bk = k;
            }
        }
        d_maxov[idx]  = __fdiv_rn(bn, bd);   // same div.rn as reference's winner
        d_assign[idx] = bk;
    } else if (idx < n_total + K) {
        // gt class = argmax of one-hot row (first max, strict >)
        int k = idx - n_total;
        const float* row = gtl + (long)k * C;
        float best = row[0];
        int bi = 0;
        for (int c = 1; c < C; c++) {
            float v = row[c];
            if (v > best) { best = v; bi = c; }
        }
        d_gtcls[k] = bi;
    }
}

// ---------------------------------------------------------------------------
// Stage 2: ordered selection, single block of 512 threads.
// fg_sorted semantics: fg indices ascending (we need only the first 64);
// bg_sorted semantics: bg indices ascending followed by non-bg ascending
// (we need the first 256 of each stream to cover all 256 slots).
// Early exit once fg>=64 and bg>=256: min() caps in stage 3 then make the
// exact totals irrelevant.
// ---------------------------------------------------------------------------
__global__ __launch_bounds__(512)
void pt_select_kernel(int n_total)
{
    __shared__ int wcnt[16];
    const unsigned FULL = 0xffffffffu;
    int tid = threadIdx.x, lane = tid & 31, wid = tid >> 5;
    const int nwarp = 16;

    int fg_base = 0, bg_base = 0, nb_base = 0;
    for (int s = 0; s < n_total; s += 512) {
        int idx = s + tid;
        bool in = idx < n_total;
        float m = in ? d_maxov[idx] : -1.0f;
        bool fg = in && (m >= 0.5f);
        bool bg = in && (m < 0.5f) && (m >= 0.1f);
        bool nb = in && !bg;

        unsigned fgm = __ballot_sync(FULL, fg);
        unsigned bgm = __ballot_sync(FULL, bg);
        unsigned nbm = __ballot_sync(FULL, nb);
        unsigned ltm = (1u << lane) - 1u;

        if (lane == 0)
            wcnt[wid] = __popc(fgm) | (__popc(bgm) << 10) | (__popc(nbm) << 20);
        __syncthreads();

        int v = (lane < nwarp) ? wcnt[lane] : 0;
        #pragma unroll
        for (int d = 1; d < 32; d <<= 1) {
            int t = __shfl_up_sync(FULL, v, d);
            if (lane >= d) v += t;
        }
        int tot  = __shfl_sync(FULL, v, nwarp - 1);
        int excl = __shfl_sync(FULL, v, (wid > 0) ? (wid - 1) : 0);
        if (wid == 0) excl = 0;

        int fg_off = fg_base + (excl & 0x3ff)          + __popc(fgm & ltm);
        int bg_off = bg_base + ((excl >> 10) & 0x3ff)  + __popc(bgm & ltm);
        int nb_off = nb_base + ((excl >> 20) & 0x3ff)  + __popc(nbm & ltm);

        if (fg && fg_off < 64)  d_fg[fg_off] = idx;
        if (bg && bg_off < 256) d_bg[bg_off] = idx;
        if (nb && nb_off < 256) d_nb[nb_off] = idx;

        fg_base += tot & 0x3ff;
        bg_base += (tot >> 10) & 0x3ff;
        nb_base += (tot >> 20) & 0x3ff;
        __syncthreads();            // protect wcnt before next chunk overwrites
        if (fg_base >= 64 && bg_base >= 256) break;
    }
    if (tid == 0) { d_counts[0] = fg_base; d_counts[1] = bg_base; }
}

// ---------------------------------------------------------------------------
// Stage 3: per-slot outputs. out layout (float32, concatenated tuple):
//   [0,          B*4)           rois          (B x 4)
//   [B*4,        B*4 + B*C)     labels onehot (B x C)
//   [B*4 + B*C,  B*4 + 5*B*C)   bbox targets  (B x 4C)
// ---------------------------------------------------------------------------
__global__ void pt_output_kernel(const float* __restrict__ props,
                                 const float* __restrict__ gtb,
                                 int N, int K, int C, int B, int FGR,
                                 float* __restrict__ out)
{
    int slot = blockIdx.x;
    int n_fg = d_counts[0], n_bg = d_counts[1];
    int fgc = min(FGR, n_fg);
    bool isfg = slot < fgc;           // fg slots are always "valid"
    int keep;
    if (isfg) {
        keep = d_fg[slot];
    } else {
        int j = slot - fgc;           // 0 <= j <= B-1 < 256
        keep = (j < n_bg) ? d_bg[j] : d_nb[j - n_bg];
    }
    int ga  = d_assign[keep];
    int lab = isfg ? d_gtcls[ga] : 0;

    float4 roi = (keep < N) ? reinterpret_cast<const float4*>(props)[keep]
                            : reinterpret_cast<const float4*>(gtb)[keep - N];
    float4 g = reinterpret_cast<const float4*>(gtb)[ga];

    float ew  = roi.z - roi.x + 1.0f;
    float eh  = roi.w - roi.y + 1.0f;
    float ecx = roi.x + 0.5f * ew;
    float ecy = roi.y + 0.5f * eh;
    float gw  = g.z - g.x + 1.0f;
    float gh  = g.w - g.y + 1.0f;
    float gcx = g.x + 0.5f * gw;
    float gcy = g.y + 0.5f * gh;
    float tx = (gcx - ecx) / ew;
    float ty = (gcy - ecy) / eh;
    float tw = logf(gw / ew);
    float th = logf(gh / eh);

    int tid = threadIdx.x;
    if (tid < 4) {
        float v = (tid == 0) ? roi.x : (tid == 1) ? roi.y : (tid == 2) ? roi.z : roi.w;
        out[slot * 4 + tid] = v;
    }
    float* labout = out + (long)B * 4;
    for (int c = tid; c < C; c += blockDim.x)
        labout[(long)slot * C + c] = (c == lab) ? 1.0f : 0.0f;

    float4* bb = reinterpret_cast<float4*>(out + (long)B * 4 + (long)B * C);
    float4 t = make_float4(tx, ty, tw, th);
    float4 z = make_float4(0.0f, 0.0f, 0.0f, 0.0f);
    for (int c = tid; c < C; c += blockDim.x)
        bb[(long)slot * C + c] = (lab > 0 && c == lab) ? t : z;
}

// ---------------------------------------------------------------------------
extern "C" void kernel_launch(void* const* d_in, const int* in_sizes, int n_in,
                              void* d_out, int out_size)
{
    const float* props = (const float*)d_in[0];   // [1, N, 4]
    const float* gtl   = (const float*)d_in[1];   // [1, K, C]
    const float* gtb   = (const float*)d_in[2];   // [1, K, 4]

    int N = in_sizes[0] / 4;
    int K = in_sizes[2] / 4;
    int C = in_sizes[1] / K;
    int n_total = N + K;
    // out_size = B*4 + B*C + B*4C = B*(4 + 5C)
    int B   = out_size / (4 + 5 * C);   // 256
    int FGR = B / 4;                    // 64  (FG_FRACTION = 0.25)

    float* out = (float*)d_out;

    int total_threads = n_total + K;    // extra K threads compute gt_cls
    int blocks = (total_threads + 255) / 256;
    pt_iou_kernel<<<blocks, 256>>>(props, gtb, gtl, N, K, C);
    pt_select_kernel<<<1, 512>>>(n_total);
    pt_output_kernel<<<B, 128>>>(props, gtb, N, K, C, B, FGR, out);
}

// round 14
// speedup vs baseline: 1.0051x; 1.0051x over previous
#include <cuda_runtime.h>
#include <math.h>

// ---------------------------------------------------------------------------
// ProposalTarget for GB300.
// Stage 1: per-roi IoU max/argmax vs gt boxes (heavy: 50500 x 500 pairs)
// Stage 2: ordered fg/bg/non-bg index selection (single block, ballot scan)
// Stage 3: materialize rois / one-hot labels / bbox targets (256 slots)
// ---------------------------------------------------------------------------

#define MAXK   1024     // max gt boxes supported
#define MAXTOT 52224    // max total rois (N + K)

__device__ float d_maxov[MAXTOT];
__device__ int   d_assign[MAXTOT];
__device__ int   d_gtcls[MAXK];
__device__ int   d_fg[64];
__device__ int   d_bg[256];
__device__ int   d_nb[256];
__device__ int   d_counts[2];

// ---------------------------------------------------------------------------
// Stage 1: max/argmax IoU per roi + gt class argmax.
// Arithmetic for iw/ih/inter/den follows the reference op order exactly with
// round-to-nearest intrinsics (no FMA contraction) so the threshold-feeding
// quotient bn/bd is bit-identical to the reference's winning IoU.
// Argmax uses cross-multiplied comparison to avoid a divide per pair.
// ---------------------------------------------------------------------------
__global__ __launch_bounds__(256)
void pt_iou_kernel(const float* __restrict__ props,
                   const float* __restrict__ gtb,
                   const float* __restrict__ gtl,
                   int N, int K, int C)
{
    __shared__ float4 sg[MAXK];
    __shared__ float  sarea[MAXK];
    int tid = threadIdx.x;
    for (int k = tid; k < K; k += blockDim.x) {
        float4 b = reinterpret_cast<const float4*>(gtb)[k];
        sg[k] = b;
        float bw = __fadd_rn(__fsub_rn(b.z, b.x), 1.0f);
        float bh = __fadd_rn(__fsub_rn(b.w, b.y), 1.0f);
        sarea[k] = __fmul_rn(bw, bh);
    }
    __syncthreads();

    int idx = blockIdx.x * blockDim.x + tid;
    int n_total = N + K;
    if (idx < n_total) {
        float4 a = (idx < N) ? reinterpret_cast<const float4*>(props)[idx]
                             : reinterpret_cast<const float4*>(gtb)[idx - N];
        float aw = __fadd_rn(__fsub_rn(a.z, a.x), 1.0f);
        float ah = __fadd_rn(__fsub_rn(a.w, a.y), 1.0f);
        float areaA = __fmul_rn(aw, ah);

        float bn = -1.0f;   // best numerator (inter); -1 guarantees k=0 wins first
        float bd = 1.0f;    // best denominator (always > 0 afterwards)
        int   bk = 0;
        #pragma unroll 4
        for (int k = 0; k < K; k++) {
            float4 b = sg[k];
            float iw = fmaxf(__fadd_rn(__fsub_rn(fminf(a.z, b.z), fmaxf(a.x, b.x)), 1.0f), 0.0f);
            float ih = fmaxf(__fadd_rn(__fsub_rn(fminf(a.w, b.w), fmaxf(a.y, b.y)), 1.0f), 0.0f);
            float inter = __fmul_rn(iw, ih);
            float den   = __fsub_rn(__fadd_rn(areaA, sarea[k]), inter);
            // inter/den > bn/bd  <=>  inter*bd > bn*den  (all positive after k=0)
            if (__fmul_rn(inter, bd) > __fmul_rn(bn, den)) {
                bn = inter; bd = den; bk = k;
            }
        }
        d_maxov[idx]  = __fdiv_rn(bn, bd);   // same div.rn as reference's winner
        d_assign[idx] = bk;
    } else if (idx < n_total + K) {
        // gt class = argmax of one-hot row (first max, strict >)
        int k = idx - n_total;
        const float* row = gtl + (long)k * C;
        float best = row[0];
        int bi = 0;
        for (int c = 1; c < C; c++) {
            float v = row[c];
            if (v > best) { best = v; bi = c; }
        }
        d_gtcls[k] = bi;
    }
}

// ---------------------------------------------------------------------------
// Stage 2: ordered selection, single block of 512 threads.
// fg_sorted semantics: fg indices ascending (we need only the first 64);
// bg_sorted semantics: bg indices ascending followed by non-bg ascending
// (we need the first 256 of each stream to cover all 256 slots).
// Early exit once fg>=64 and bg>=256: min() caps in stage 3 then make the
// exact totals irrelevant.
// ---------------------------------------------------------------------------
__global__ __launch_bounds__(512)
void pt_select_kernel(int n_total)
{
    __shared__ int wcnt[16];
    const unsigned FULL = 0xffffffffu;
    int tid = threadIdx.x, lane = tid & 31, wid = tid >> 5;
    const int nwarp = 16;

    int fg_base = 0, bg_base = 0, nb_base = 0;
    for (int s = 0; s < n_total; s += 512) {
        int idx = s + tid;
        bool in = idx < n_total;
        float m = in ? d_maxov[idx] : -1.0f;
        bool fg = in && (m >= 0.5f);
        bool bg = in && (m < 0.5f) && (m >= 0.1f);
        bool nb = in && !bg;

        unsigned fgm = __ballot_sync(FULL, fg);
        unsigned bgm = __ballot_sync(FULL, bg);
        unsigned nbm = __ballot_sync(FULL, nb);
        unsigned ltm = (1u << lane) - 1u;

        if (lane == 0)
            wcnt[wid] = __popc(fgm) | (__popc(bgm) << 10) | (__popc(nbm) << 20);
        __syncthreads();

        int v = (lane < nwarp) ? wcnt[lane] : 0;
        #pragma unroll
        for (int d = 1; d < 32; d <<= 1) {
            int t = __shfl_up_sync(FULL, v, d);
            if (lane >= d) v += t;
        }
        int tot  = __shfl_sync(FULL, v, nwarp - 1);
        int excl = __shfl_sync(FULL, v, (wid > 0) ? (wid - 1) : 0);
        if (wid == 0) excl = 0;

        int fg_off = fg_base + (excl & 0x3ff)          + __popc(fgm & ltm);
        int bg_off = bg_base + ((excl >> 10) & 0x3ff)  + __popc(bgm & ltm);
        int nb_off = nb_base + ((excl >> 20) & 0x3ff)  + __popc(nbm & ltm);

        if (fg && fg_off < 64)  d_fg[fg_off] = idx;
        if (bg && bg_off < 256) d_bg[bg_off] = idx;
        if (nb && nb_off < 256) d_nb[nb_off] = idx;

        fg_base += tot & 0x3ff;
        bg_base += (tot >> 10) & 0x3ff;
        nb_base += (tot >> 20) & 0x3ff;
        __syncthreads();            // protect wcnt before next chunk overwrites
        if (fg_base >= 64 && bg_base >= 256) break;
    }
    if (tid == 0) { d_counts[0] = fg_base; d_counts[1] = bg_base; }
}

// ---------------------------------------------------------------------------
// Stage 3: per-slot outputs. out layout (float32, concatenated tuple):
//   [0,          B*4)           rois          (B x 4)
//   [B*4,        B*4 + B*C)     labels onehot (B x C)
//   [B*4 + B*C,  B*4 + 5*B*C)   bbox targets  (B x 4C)
// ---------------------------------------------------------------------------
__global__ void pt_output_kernel(const float* __restrict__ props,
                                 const float* __restrict__ gtb,
                                 int N, int K, int C, int B, int FGR,
                                 float* __restrict__ out)
{
    int slot = blockIdx.x;
    int n_fg = d_counts[0], n_bg = d_counts[1];
    int fgc = min(FGR, n_fg);
    bool isfg = slot < fgc;           // fg slots are always "valid"
    int keep;
    if (isfg) {
        keep = d_fg[slot];
    } else {
        int j = slot - fgc;           // 0 <= j <= B-1 < 256
        keep = (j < n_bg) ? d_bg[j] : d_nb[j - n_bg];
    }
    int ga  = d_assign[keep];
    int lab = isfg ? d_gtcls[ga] : 0;

    float4 roi = (keep < N) ? reinterpret_cast<const float4*>(props)[keep]
                            : reinterpret_cast<const float4*>(gtb)[keep - N];
    float4 g = reinterpret_cast<const float4*>(gtb)[ga];

    float ew  = roi.z - roi.x + 1.0f;
    float eh  = roi.w - roi.y + 1.0f;
    float ecx = roi.x + 0.5f * ew;
    float ecy = roi.y + 0.5f * eh;
    float gw  = g.z - g.x + 1.0f;
    float gh  = g.w - g.y + 1.0f;
    float gcx = g.x + 0.5f * gw;
    float gcy = g.y + 0.5f * gh;
    float tx = (gcx - ecx) / ew;
    float ty = (gcy - ecy) / eh;
    float tw = logf(gw / ew);
    float th = logf(gh / eh);

    int tid = threadIdx.x;
    if (tid < 4) {
        float v = (tid == 0) ? roi.x : (tid == 1) ? roi.y : (tid == 2) ? roi.z : roi.w;
        out[slot * 4 + tid] = v;
    }
    float* labout = out + (long)B * 4;
    for (int c = tid; c < C; c += blockDim.x)
        labout[(long)slot * C + c] = (c == lab) ? 1.0f : 0.0f;

    float4* bb = reinterpret_cast<float4*>(out + (long)B * 4 + (long)B * C);
    float4 t = make_float4(tx, ty, tw, th);
    float4 z = make_float4(0.0f, 0.0f, 0.0f, 0.0f);
    for (int c = tid; c < C; c += blockDim.x)
        bb[(long)slot * C + c] = (lab > 0 && c == lab) ? t : z;
}

// ---------------------------------------------------------------------------
extern "C" void kernel_launch(void* const* d_in, const int* in_sizes, int n_in,
                              void* d_out, int out_size)
{
    const float* props = (const float*)d_in[0];   // [1, N, 4]
    const float* gtl   = (const float*)d_in[1];   // [1, K, C]
    const float* gtb   = (const float*)d_in[2];   // [1, K, 4]

    int N = in_sizes[0] / 4;
    int K = in_sizes[2] / 4;
    int C = in_sizes[1] / K;
    int n_total = N + K;
    // out_size = B*4 + B*C + B*4C = B*(4 + 5C)
    int B   = out_size / (4 + 5 * C);   // 256
    int FGR = B / 4;                    // 64  (FG_FRACTION = 0.25)

    float* out = (float*)d_out;

    int total_threads = n_total + K;    // extra K threads compute gt_cls
    int blocks = (total_threads + 255) / 256;
    pt_iou_kernel<<<blocks, 256>>>(props, gtb, gtl, N, K, C);
    pt_select_kernel<<<1, 512>>>(n_total);
    pt_output_kernel<<<B, 128>>>(props, gtb, N, K, C, B, FGR, out);
}